// round 1
// baseline (speedup 1.0000x reference)
#include <cuda_runtime.h>

// ---------------------------------------------------------------------------
// VQ_16243566313849 : fused 1x1-conv projection + nearest-codebook argmin +
// gather, full fp32 precision, Blackwell packed fma.rn.f32x2 hot loop.
//
// Shapes: z (B=8, CIN=768, N=4096), W (Q=128, CIN=768), emb (K=4096, Q=128)
// out (B, Q=128, N=4096) fp32.
// ---------------------------------------------------------------------------

namespace {
constexpr int Bn  = 8;
constexpr int CIN = 768;
constexpr int Qd  = 128;
constexpr int Kn  = 4096;
constexpr int Nn  = 4096;

constexpr int TN  = 128;  // n-tile per block
constexpr int KT  = 64;   // k-tile (codebook rows per inner tile)
constexpr int CK  = 32;   // c-chunk for phase-1 GEMM

// shared memory layout (float offsets)
constexpr int ZE_STR   = 132;                 // padded stride for 128-wide rows
constexpr int ET_STR   = 68;                  // padded stride for KT=64 rows
constexpr int ZE_OFF   = 0;                   // ze tile: 128 x ZE_STR
constexpr int ZSQ_OFF  = ZE_OFF + Qd * ZE_STR;        // 16896, 128 floats
constexpr int SQS_OFF  = ZSQ_OFF + 128;               // 17024, 64 floats
constexpr int IDX_OFF  = SQS_OFF + 64;                // 17088, 128 ints
constexpr int R2_OFF   = 17216;               // union: et (128x68=8704) |
                                              //        Wt(32x132)+zt(32x132)=8448 |
                                              //        reduce rv(1024)+ri(1024)
constexpr int SMEM_FLOATS = R2_OFF + Qd * ET_STR;     // 25920
constexpr int SMEM_BYTES  = SMEM_FLOATS * 4;          // 103680 B -> 2 blocks/SM
}

__device__ float d_emb_sq[Kn];

// ---- packed fp32x2 helpers (Blackwell) ------------------------------------
__device__ __forceinline__ void fma2(unsigned long long& acc,
                                     unsigned long long a,
                                     unsigned long long b) {
    asm("fma.rn.f32x2 %0, %1, %2, %0;" : "+l"(acc) : "l"(a), "l"(b));
}
__device__ __forceinline__ unsigned long long dup2(float x) {
    unsigned long long r;
    unsigned int u = __float_as_uint(x);
    asm("mov.b64 %0, {%1, %1};" : "=l"(r) : "r"(u));
    return r;
}
__device__ __forceinline__ void unpack2(float& lo, float& hi,
                                        unsigned long long v) {
    unsigned int a, b2;
    asm("mov.b64 {%0, %1}, %2;" : "=r"(a), "=r"(b2) : "l"(v));
    lo = __uint_as_float(a);
    hi = __uint_as_float(b2);
}

// ---- emb row squared norms ------------------------------------------------
__global__ void embsq_kernel(const float* __restrict__ emb) {
    int w    = (blockIdx.x * blockDim.x + threadIdx.x) >> 5;
    int lane = threadIdx.x & 31;
    if (w >= Kn) return;
    const float* row = emb + (size_t)w * Qd;
    float s = 0.0f;
    #pragma unroll
    for (int j = 0; j < Qd / 32; ++j) {
        float v = row[lane + j * 32];
        s = fmaf(v, v, s);
    }
    #pragma unroll
    for (int off = 16; off > 0; off >>= 1)
        s += __shfl_down_sync(0xffffffffu, s, off);
    if (lane == 0) d_emb_sq[w] = s;
}

// ---- fused main kernel ----------------------------------------------------
__global__ void __launch_bounds__(256, 2)
vq_main_kernel(const float* __restrict__ z, const float* __restrict__ W,
               const float* __restrict__ emb, float* __restrict__ out) {
    extern __shared__ float sm[];
    float* ze_s  = sm + ZE_OFF;
    float* zsq_s = sm + ZSQ_OFF;
    float* sq_s  = sm + SQS_OFF;
    int*   idx_s = reinterpret_cast<int*>(sm + IDX_OFF);
    float* r2    = sm + R2_OFF;

    const int tid = threadIdx.x;
    const int b   = blockIdx.y;
    const int n0  = blockIdx.x * TN;

    // =============== Phase 1: ze tile = W @ z[b][:, n0:n0+128] =============
    {
        float* Wt = r2;                 // [CK][ZE_STR]  (transposed: [c][q])
        float* zt = r2 + CK * ZE_STR;   // [CK][ZE_STR]  ([c][n])
        const int ty1 = tid >> 4;       // 0..15 -> q rows ty1*8..+7
        const int tx1 = tid & 15;       // 0..15 -> n cols tx1*8..+7

        unsigned long long acc1[8][4];
        #pragma unroll
        for (int i = 0; i < 8; ++i)
            #pragma unroll
            for (int j = 0; j < 4; ++j) acc1[i][j] = 0ull;

        for (int c0 = 0; c0 < CIN; c0 += CK) {
            for (int i = tid; i < CK * Qd; i += 256) {
                int c = i & (CK - 1);
                int q = i >> 5;
                Wt[c * ZE_STR + q] = W[q * CIN + c0 + c];
            }
            const float* zsrc = z + ((size_t)b * CIN + c0) * Nn + n0;
            for (int i = tid; i < CK * TN; i += 256) {
                int nn = i & 127;
                int r  = i >> 7;
                zt[r * ZE_STR + nn] = zsrc[(size_t)r * Nn + nn];
            }
            __syncthreads();
            #pragma unroll 4
            for (int c = 0; c < CK; ++c) {
                const float4 av0 =
                    *reinterpret_cast<const float4*>(Wt + c * ZE_STR + ty1 * 8);
                const float4 av1 =
                    *reinterpret_cast<const float4*>(Wt + c * ZE_STR + ty1 * 8 + 4);
                const ulonglong2 bv0 =
                    *reinterpret_cast<const ulonglong2*>(zt + c * ZE_STR + tx1 * 8);
                const ulonglong2 bv1 =
                    *reinterpret_cast<const ulonglong2*>(zt + c * ZE_STR + tx1 * 8 + 4);
                const unsigned long long bp0 = bv0.x, bp1 = bv0.y;
                const unsigned long long bp2 = bv1.x, bp3 = bv1.y;
                const float a[8] = {av0.x, av0.y, av0.z, av0.w,
                                    av1.x, av1.y, av1.z, av1.w};
                #pragma unroll
                for (int i = 0; i < 8; ++i) {
                    const unsigned long long ad = dup2(a[i]);
                    fma2(acc1[i][0], ad, bp0);
                    fma2(acc1[i][1], ad, bp1);
                    fma2(acc1[i][2], ad, bp2);
                    fma2(acc1[i][3], ad, bp3);
                }
            }
            __syncthreads();
        }
        // store ze tile: ze_s[q][n]
        #pragma unroll
        for (int i = 0; i < 8; ++i) {
            float* rowp = ze_s + (ty1 * 8 + i) * ZE_STR + tx1 * 8;
            *reinterpret_cast<ulonglong2*>(rowp) =
                make_ulonglong2(acc1[i][0], acc1[i][1]);
            *reinterpret_cast<ulonglong2*>(rowp + 4) =
                make_ulonglong2(acc1[i][2], acc1[i][3]);
        }
    }
    __syncthreads();

    // per-column ||ze||^2
    if (tid < 128) {
        float s = 0.0f;
        #pragma unroll 8
        for (int q = 0; q < Qd; ++q) {
            float v = ze_s[q * ZE_STR + tid];
            s = fmaf(v, v, s);
        }
        zsq_s[tid] = s;
    }
    __syncthreads();

    // =============== Phase 2: argmin_k ( (zsq - 2<emb_k, ze_n>) + |emb_k|^2 )
    const int ty2 = tid >> 5;  // 0..7  -> k rows ty2*8..+7 in tile
    const int tx2 = tid & 31;  // 0..31 -> n cols tx2*4..+3
    float* et = r2;            // [q][k_local], stride ET_STR

    float zqv[4];
    #pragma unroll
    for (int jj = 0; jj < 4; ++jj) zqv[jj] = zsq_s[tx2 * 4 + jj];

    float minv[4] = {3.402823466e38f, 3.402823466e38f,
                     3.402823466e38f, 3.402823466e38f};
    int   mini[4] = {0, 0, 0, 0};

    for (int kt = 0; kt < Kn; kt += KT) {
        // stage emb tile transposed: et[q][kl] = emb[kt+kl][q]
        for (int i = tid; i < KT * Qd; i += 256) {
            int kl = i >> 7;
            int qq = i & 127;
            et[qq * ET_STR + kl] = emb[(size_t)(kt + kl) * Qd + qq];
        }
        if (tid < KT) sq_s[tid] = d_emb_sq[kt + tid];
        __syncthreads();

        unsigned long long acc[4][4];
        #pragma unroll
        for (int i = 0; i < 4; ++i)
            #pragma unroll
            for (int j = 0; j < 4; ++j) acc[i][j] = 0ull;

        #pragma unroll 4
        for (int q = 0; q < Qd; ++q) {
            const ulonglong2 a01 =
                *reinterpret_cast<const ulonglong2*>(et + q * ET_STR + ty2 * 8);
            const ulonglong2 a23 =
                *reinterpret_cast<const ulonglong2*>(et + q * ET_STR + ty2 * 8 + 4);
            const float4 bv =
                *reinterpret_cast<const float4*>(ze_s + q * ZE_STR + tx2 * 4);
            const unsigned long long bd0 = dup2(bv.x), bd1 = dup2(bv.y);
            const unsigned long long bd2 = dup2(bv.z), bd3 = dup2(bv.w);
            fma2(acc[0][0], a01.x, bd0); fma2(acc[0][1], a01.x, bd1);
            fma2(acc[0][2], a01.x, bd2); fma2(acc[0][3], a01.x, bd3);
            fma2(acc[1][0], a01.y, bd0); fma2(acc[1][1], a01.y, bd1);
            fma2(acc[1][2], a01.y, bd2); fma2(acc[1][3], a01.y, bd3);
            fma2(acc[2][0], a23.x, bd0); fma2(acc[2][1], a23.x, bd1);
            fma2(acc[2][2], a23.x, bd2); fma2(acc[2][3], a23.x, bd3);
            fma2(acc[3][0], a23.y, bd0); fma2(acc[3][1], a23.y, bd1);
            fma2(acc[3][2], a23.y, bd2); fma2(acc[3][3], a23.y, bd3);
        }

        // epilogue: d2 = (zsq - 2*cross) + emb_sq, strict-< keeps lowest k
        #pragma unroll
        for (int ip = 0; ip < 4; ++ip) {
            const int   ka  = kt + ty2 * 8 + 2 * ip;
            const float sqa = sq_s[ty2 * 8 + 2 * ip];
            const float sqb = sq_s[ty2 * 8 + 2 * ip + 1];
            #pragma unroll
            for (int jj = 0; jj < 4; ++jj) {
                float lo, hi;
                unpack2(lo, hi, acc[ip][jj]);
                const float d2a = fmaf(-2.0f, lo, zqv[jj]) + sqa;
                const float d2b = fmaf(-2.0f, hi, zqv[jj]) + sqb;
                if (d2a < minv[jj]) { minv[jj] = d2a; mini[jj] = ka; }
                if (d2b < minv[jj]) { minv[jj] = d2b; mini[jj] = ka + 1; }
            }
        }
        __syncthreads();
    }

    // =============== cross-thread argmin reduction (lowest-k tie-break) ====
    {
        float* rv = r2;                                   // [8][128]
        int*   ri = reinterpret_cast<int*>(r2 + 1024);    // [8][128]
        #pragma unroll
        for (int jj = 0; jj < 4; ++jj) {
            rv[ty2 * 128 + tx2 * 4 + jj] = minv[jj];
            ri[ty2 * 128 + tx2 * 4 + jj] = mini[jj];
        }
        __syncthreads();
        if (tid < 128) {
            float bv2 = rv[tid];
            int   bi  = ri[tid];
            #pragma unroll
            for (int t = 1; t < 8; ++t) {
                float v  = rv[t * 128 + tid];
                int   ix = ri[t * 128 + tid];
                if (v < bv2 || (v == bv2 && ix < bi)) { bv2 = v; bi = ix; }
            }
            idx_s[tid] = bi;
        }
        __syncthreads();
    }

    // =============== gather: out[b][q][n] = emb[idx[n]][q] =================
    {
        float* buf = sm;  // reuse ze region, stride 129 (conflict-free)
        for (int i = tid; i < Qd * TN; i += 256) {
            int n  = i >> 7;
            int qq = i & 127;
            buf[n * 129 + qq] = emb[(size_t)idx_s[n] * Qd + qq];
        }
        __syncthreads();
        for (int i = tid; i < Qd * TN; i += 256) {
            int qq = i >> 7;
            int n  = i & 127;
            out[((size_t)b * Qd + qq) * Nn + n0 + n] = buf[n * 129 + qq];
        }
    }
}

// ---------------------------------------------------------------------------
extern "C" void kernel_launch(void* const* d_in, const int* in_sizes, int n_in,
                              void* d_out, int out_size) {
    const float* z   = nullptr;
    const float* W   = nullptr;
    const float* emb = nullptr;
    for (int i = 0; i < n_in; ++i) {
        if (in_sizes[i] == Bn * CIN * Nn)      z   = (const float*)d_in[i];
        else if (in_sizes[i] == Qd * CIN)      W   = (const float*)d_in[i];
        else if (in_sizes[i] == Kn * Qd)       emb = (const float*)d_in[i];
    }
    float* out = (float*)d_out;

    cudaFuncSetAttribute(vq_main_kernel,
                         cudaFuncAttributeMaxDynamicSharedMemorySize,
                         SMEM_BYTES);

    embsq_kernel<<<Kn * 32 / 256, 256>>>(emb);
    dim3 grid(Nn / TN, Bn);
    vq_main_kernel<<<grid, 256, SMEM_BYTES>>>(z, W, emb, out);
}